// round 9
// baseline (speedup 1.0000x reference)
#include <cuda_runtime.h>
#include <cuda_bf16.h>
#include <cstdint>

// Problem: B=128, N=128, D=1024, H=8, HD=128, M = B*N = 16384
#define PLANE    (16384ull * 1024ull)   // activation plane elems
#define WPLANE_F (1024ull * 1024ull)    // f32 weight plane elems
__device__ __align__(1024) __nv_bfloat16 g_bf[22ull * PLANE + 16ull * WPLANE_F + 16ull * WPLANE_F];

typedef __nv_bfloat16 bf16;

// ======================= PTX helpers =========================================
__device__ __forceinline__ uint32_t s2u(const void* p) {
    uint32_t a;
    asm("{ .reg .u64 t; cvta.to.shared.u64 t, %1; cvt.u32.u64 %0, t; }"
        : "=r"(a) : "l"(p));
    return a;
}
__device__ __forceinline__ void ldsm4(uint32_t* r, uint32_t addr) {
    asm volatile("ldmatrix.sync.aligned.m8n8.x4.shared.b16 {%0,%1,%2,%3}, [%4];"
                 : "=r"(r[0]), "=r"(r[1]), "=r"(r[2]), "=r"(r[3]) : "r"(addr));
}
__device__ __forceinline__ void ldsm4t(uint32_t* r, uint32_t addr) {
    asm volatile("ldmatrix.sync.aligned.m8n8.x4.trans.shared.b16 {%0,%1,%2,%3}, [%4];"
                 : "=r"(r[0]), "=r"(r[1]), "=r"(r[2]), "=r"(r[3]) : "r"(addr));
}
__device__ __forceinline__ void mma_bf16(float* d, const uint32_t* a, const uint32_t* b) {
    asm volatile(
        "mma.sync.aligned.m16n8k16.row.col.f32.bf16.bf16.f32 "
        "{%0,%1,%2,%3},{%4,%5,%6,%7},{%8,%9},{%0,%1,%2,%3};"
        : "+f"(d[0]), "+f"(d[1]), "+f"(d[2]), "+f"(d[3])
        : "r"(a[0]), "r"(a[1]), "r"(a[2]), "r"(a[3]), "r"(b[0]), "r"(b[1]));
}
__device__ __forceinline__ void mma_tf32(float* d, const uint32_t* a, const uint32_t* b) {
    asm volatile(
        "mma.sync.aligned.m16n8k8.row.col.f32.tf32.tf32.f32 "
        "{%0,%1,%2,%3},{%4,%5,%6,%7},{%8,%9},{%0,%1,%2,%3};"
        : "+f"(d[0]), "+f"(d[1]), "+f"(d[2]), "+f"(d[3])
        : "r"(a[0]), "r"(a[1]), "r"(a[2]), "r"(a[3]), "r"(b[0]), "r"(b[1]));
}
#define CP16(dst, src) \
    asm volatile("cp.async.cg.shared.global [%0], [%1], 16;" :: "r"(dst), "l"(src))
#define CPCOMMIT() asm volatile("cp.async.commit_group;" ::: "memory")
#define CPWAIT2()  asm volatile("cp.async.wait_group 2;" ::: "memory")
#define CPWAIT0()  asm volatile("cp.async.wait_group 0;" ::: "memory")

__device__ __forceinline__ float tf32r(float x) {   // round-to-nearest tf32
    uint32_t u; asm("cvt.rna.tf32.f32 %0, %1;" : "=r"(u) : "f"(x));
    return __uint_as_float(u);
}
__device__ __forceinline__ void split1(float v, bf16& h, bf16& l) {
    h = __float2bfloat16(v);
    l = __float2bfloat16(v - __bfloat162float(h));
}
__device__ __forceinline__ void packsplit2(float x0, float x1,
                                           uint32_t& hi, uint32_t& lo) {
    bf16 h0, l0, h1, l1;
    split1(x0, h0, l0); split1(x1, h1, l1);
    __nv_bfloat162 hh; hh.x = h0; hh.y = h1;
    __nv_bfloat162 ll; ll.x = l0; ll.y = l1;
    hi = *(uint32_t*)&hh; lo = *(uint32_t*)&ll;
}

// ======================= input rounding (3 inputs -> tf32 f32 planes) ========
__global__ __launch_bounds__(256) void split_all(
    const float* __restrict__ s0, const float* __restrict__ s1,
    const float* __restrict__ s2, float* __restrict__ ob)
{
    const float* src = (blockIdx.y == 0) ? s0 : (blockIdx.y == 1) ? s1 : s2;
    float* o = ob + (size_t)blockIdx.y * PLANE;
    size_t i4 = ((size_t)blockIdx.x * 256 + threadIdx.x) * 4;
    float4 v = *(const float4*)(src + i4);
    v.x = tf32r(v.x); v.y = tf32r(v.y); v.z = tf32r(v.z); v.w = tf32r(v.w);
    *(float4*)(o + i4) = v;
}

// ======================= weight transpose -> tf32 f32 planes (4 each) ========
__global__ __launch_bounds__(256) void transpose4(
    const float* __restrict__ s0, const float* __restrict__ s1,
    const float* __restrict__ s2, const float* __restrict__ s3,
    float* __restrict__ ob)
{
    const float* src = (blockIdx.z == 0) ? s0 : (blockIdx.z == 1) ? s1
                     : (blockIdx.z == 2) ? s2 : s3;
    float* o = ob + (size_t)blockIdx.z * WPLANE_F;
    __shared__ float t[32][33];
    int bx = blockIdx.x * 32, by = blockIdx.y * 32;
    int tx = threadIdx.x, ty = threadIdx.y;
#pragma unroll
    for (int i = ty; i < 32; i += 8)
        t[i][tx] = src[(size_t)(by + i) * 1024 + bx + tx];
    __syncthreads();
#pragma unroll
    for (int i = ty; i < 32; i += 8)
        o[(size_t)(bx + i) * 1024 + by + tx] = tf32r(t[tx][i]);
}

// ======================= single-pass tf32 mma.sync GEMM ======================
// CTA tile 128x64, 256 thr, warp grid 4(m) x 2(n): warp tile 32x32.
// 3 CTAs/SM target (launch_bounds reg cap 85). k16 chunks, 4-stage ring.
// smem stage: A@0 (128 rows x 80B = 10240), B@10240 (64 x 80B = 5120); stride 15360.
// A idx(r,k) = (r/128)*131072 + (k/128)*ACB + (r%128)*ARI + (k%128)
// Column tile ct: plane bp = ct>>4, in-plane tile bct = ct&15 (64 cols each).
#define GEMM_SMEM (4 * 15360)

__global__ __launch_bounds__(256, 3) void gemm_tf(
    const float* __restrict__ A, const float* __restrict__ B,
    float* __restrict__ Cf, bf16* __restrict__ Ch, bf16* __restrict__ Cl,
    const float* __restrict__ bias, int ACB, int ARI, int CCB, int CRI)
{
    extern __shared__ __align__(1024) char smem[];
    const uint32_t sb = s2u(smem);
    const int tid = threadIdx.x;
    const int lane = tid & 31, wid = tid >> 5;
    const int rt = blockIdx.y, ct = blockIdx.x;
    const int bp = ct >> 4, bct = ct & 15;
    const int wm = wid & 3, wn = wid >> 2;
    // tf32-frag ldsm lane offsets (f32 tiles viewed as b16 double-width)
    const uint32_t aLane = (uint32_t)((lane & 15) * 80 + (lane >> 4) * 16);
    const uint32_t bLane = (uint32_t)(((lane & 7) + (lane >> 4) * 8) * 80
                                      + ((lane >> 3) & 1) * 16);

    const int lrow = tid >> 2, seg = tid & 3;
    const uint32_t dstoff = (uint32_t)(lrow * 80 + seg * 16);

    float acc[2][4][4];
#pragma unroll
    for (int i = 0; i < 2; i++)
#pragma unroll
        for (int j = 0; j < 4; j++)
#pragma unroll
            for (int k = 0; k < 4; k++) acc[i][j][k] = 0.f;

    auto load_chunk = [&](int c) {
        const int kk = c * 16;
        const uint32_t st = sb + (uint32_t)((c & 3) * 15360);
#pragma unroll
        for (int p = 0; p < 2; p++) {
            const int row = lrow + p * 64;
            const size_t asrc = (size_t)rt * 131072 + (size_t)(kk >> 7) * ACB
                              + (size_t)row * ARI + (kk & 127) + seg * 4;
            CP16(st + dstoff + (uint32_t)(p * 5120), A + asrc);
        }
        const size_t bsrc = (size_t)bp * WPLANE_F
                          + (size_t)(bct * 64 + lrow) * 1024 + kk + seg * 4;
        CP16(st + 10240u + dstoff, B + bsrc);
    };

    load_chunk(0); CPCOMMIT();
    load_chunk(1); CPCOMMIT();
    load_chunk(2); CPCOMMIT();

    for (int c = 0; c < 64; c++) {
        CPWAIT2();
        __syncthreads();
        if (c + 3 < 64) load_chunk(c + 3);
        CPCOMMIT();

        const uint32_t off = sb + (uint32_t)((c & 3) * 15360);
        // B fragments: 2 k8 steps x 2 ldsm (each covers 2 n8-tiles)
        uint32_t bt[2][4][2];
#pragma unroll
        for (int ks = 0; ks < 2; ks++)
#pragma unroll
            for (int pr = 0; pr < 2; pr++) {
                uint32_t q[4];
                ldsm4(q, off + 10240u + (uint32_t)((wn * 32 + pr * 16) * 80)
                         + bLane + (uint32_t)(ks * 32));
                bt[ks][2 * pr][0]     = q[0]; bt[ks][2 * pr][1]     = q[1];
                bt[ks][2 * pr + 1][0] = q[2]; bt[ks][2 * pr + 1][1] = q[3];
            }
#pragma unroll
        for (int ks = 0; ks < 2; ks++) {
            uint32_t at[2][4];
#pragma unroll
            for (int mt = 0; mt < 2; mt++)
                ldsm4(at[mt], off + (uint32_t)((wm * 32 + mt * 16) * 80)
                              + aLane + (uint32_t)(ks * 32));
#pragma unroll
            for (int mt = 0; mt < 2; mt++)
#pragma unroll
                for (int nt = 0; nt < 4; nt++)
                    mma_tf32(acc[mt][nt], at[mt], bt[ks][nt]);
        }
    }

    // ---- epilogue ----
    const int g = lane >> 2, cp2 = (lane & 3) * 2;
    const size_t cbase = (size_t)bp * PLANE + (size_t)rt * 131072
                       + (size_t)(bct >> 1) * CCB + (bct & 1) * 64;
#pragma unroll
    for (int mt = 0; mt < 2; mt++) {
#pragma unroll
        for (int nt = 0; nt < 4; nt++) {
            int r0 = wm * 32 + mt * 16 + g;
            int col = wn * 32 + nt * 8 + cp2;
            float v0 = acc[mt][nt][0], v1 = acc[mt][nt][1];
            float v2 = acc[mt][nt][2], v3 = acc[mt][nt][3];
            size_t o0 = cbase + (size_t)r0 * CRI + col;
            size_t o1 = cbase + (size_t)(r0 + 8) * CRI + col;
            if (Cf) {
                float b0 = bias[bct * 64 + col], b1 = bias[bct * 64 + col + 1];
                *(float2*)(Cf + o0) = make_float2(v0 + b0, v1 + b1);
                *(float2*)(Cf + o1) = make_float2(v2 + b0, v3 + b1);
            } else {
                uint32_t hh, ll;
                packsplit2(v0, v1, hh, ll);
                *(uint32_t*)(Ch + o0) = hh; *(uint32_t*)(Cl + o0) = ll;
                packsplit2(v2, v3, hh, ll);
                *(uint32_t*)(Ch + o1) = hh; *(uint32_t*)(Cl + o1) = ll;
            }
        }
    }
}

// ======================= mma attention (bf16-split, register-resident P) =====
// One CTA per (b,h). Warp w owns rows w*16..w*16+15 (full 128 cols).
// Output: single f32 plane, tf32-rounded (feeds final tf32 GEMM).
// smem: Q stages@0 (4 x 12288: h@0 l@6144), K/V stages@49152 (4 x 8704).
#define ATT_SMEM 83968
#define ATT_KST  49152u

__global__ __launch_bounds__(256, 1) void attn_mma(
    const bf16* __restrict__ ohb, const bf16* __restrict__ olb,
    float* __restrict__ attf)
{
    extern __shared__ __align__(1024) char smem[];
    const uint32_t sb = s2u(smem);
    const int tid = threadIdx.x;
    const int lane = tid & 31, w = tid >> 5;
    const size_t bhoff = (size_t)blockIdx.x * 16384;

    // plane order in ohb: 0 qw, 1 kw, 2 vw, 3 qp, 4 kp, 5 qc, 6 kc
    const int qpl[3] = { 0, 3, 5 }, kpl[3] = { 1, 4, 6 };

    const int s8 = lane >> 3, r8 = lane & 7;
    const uint32_t aLane = (uint32_t)(((s8 & 1) * 8 + r8) * 48 + (s8 >> 1) * 16);
    const uint32_t kr = (uint32_t)(lane & 15);
    const uint32_t nf = (uint32_t)((lane >> 4) * 8);
    const uint32_t wrow48 = (uint32_t)(w * 16 * 48);

    const int qrow = tid >> 1, qhalf = tid & 1;
    const uint32_t qdst = (uint32_t)(qrow * 48 + qhalf * 16);
    const int krow = tid >> 4, kseg = tid & 15;
    const uint32_t kdst = (uint32_t)(krow * 272 + kseg * 16);

    auto loadQK = [&](int it) {
        int s = it >> 3, c = it & 7;
        uint32_t qs = sb + (uint32_t)((it & 3) * 12288) + qdst;
        size_t qsrc = (size_t)qpl[s] * PLANE + bhoff + (size_t)qrow * 128 + c * 16 + qhalf * 8;
        CP16(qs,        ohb + qsrc);
        CP16(qs + 6144, olb + qsrc);
        uint32_t ks = sb + ATT_KST + (uint32_t)((it & 3) * 8704) + kdst;
        size_t ksrc = (size_t)kpl[s] * PLANE + bhoff + (size_t)(c * 16 + krow) * 128 + kseg * 8;
        CP16(ks,        ohb + ksrc);
        CP16(ks + 4352, olb + ksrc);
    };
    auto loadV = [&](int v) {
        uint32_t ks = sb + ATT_KST + (uint32_t)((v & 3) * 8704) + kdst;
        size_t ksrc = 2ull * PLANE + bhoff + (size_t)(v * 16 + krow) * 128 + kseg * 8;
        CP16(ks,        ohb + ksrc);
        CP16(ks + 4352, olb + ksrc);
    };

    float acc[16][4];
#pragma unroll
    for (int i = 0; i < 16; i++)
#pragma unroll
        for (int j = 0; j < 4; j++) acc[i][j] = 0.f;

    loadQK(0); CPCOMMIT();
    loadQK(1); CPCOMMIT();
    loadQK(2); CPCOMMIT();

    // ---- Phase 1: sim (24 iters = 3 streams x 8 k-chunks) ----
    for (int it = 0; it < 24; it++) {
        CPWAIT2();
        __syncthreads();
        if (it + 3 < 24) loadQK(it + 3);
        CPCOMMIT();

        const uint32_t qs = sb + (uint32_t)((it & 3) * 12288);
        const uint32_t ks = sb + ATT_KST + (uint32_t)((it & 3) * 8704);
        uint32_t ah[4], al[4];
        ldsm4(ah, qs + wrow48 + aLane);
        ldsm4(al, qs + 6144 + wrow48 + aLane);
#pragma unroll
        for (int gp = 0; gp < 4; gp++) {
            uint32_t b0h[4], b0l[4], b1h[4], b1l[4];
            uint32_t a0 = ks + kr * 272 + ((2 * gp) * 16 + nf) * 2;
            uint32_t a1 = ks + kr * 272 + ((2 * gp + 1) * 16 + nf) * 2;
            ldsm4t(b0h, a0); ldsm4t(b0l, a0 + 4352);
            ldsm4t(b1h, a1); ldsm4t(b1l, a1 + 4352);
            float* c0 = acc[4 * gp],     *c1 = acc[4 * gp + 1];
            float* c2 = acc[4 * gp + 2], *c3 = acc[4 * gp + 3];
            mma_bf16(c0, ah, b0h);     mma_bf16(c1, ah, b0h + 2);
            mma_bf16(c2, ah, b1h);     mma_bf16(c3, ah, b1h + 2);
            mma_bf16(c0, al, b0h);     mma_bf16(c1, al, b0h + 2);
            mma_bf16(c2, al, b1h);     mma_bf16(c3, al, b1h + 2);
            mma_bf16(c0, ah, b0l);     mma_bf16(c1, ah, b0l + 2);
            mma_bf16(c2, ah, b1l);     mma_bf16(c3, ah, b1l + 2);
        }
    }

    // drain QK traffic, then prefetch V into stages 0..2 (overlaps softmax)
    CPWAIT0();
    __syncthreads();
    loadV(0); CPCOMMIT();
    loadV(1); CPCOMMIT();
    loadV(2); CPCOMMIT();

    // ---- Phase 2: softmax (warp-local; lane rows g and g+8) ----
    const float SC = 0.08838834764831845f;   // 128^-0.5
    float m0 = -1e30f, m1 = -1e30f;
#pragma unroll
    for (int nt = 0; nt < 16; nt++) {
#pragma unroll
        for (int j = 0; j < 4; j++) acc[nt][j] *= SC;
        m0 = fmaxf(m0, fmaxf(acc[nt][0], acc[nt][1]));
        m1 = fmaxf(m1, fmaxf(acc[nt][2], acc[nt][3]));
    }
    m0 = fmaxf(m0, __shfl_xor_sync(0xffffffffu, m0, 1));
    m0 = fmaxf(m0, __shfl_xor_sync(0xffffffffu, m0, 2));
    m1 = fmaxf(m1, __shfl_xor_sync(0xffffffffu, m1, 1));
    m1 = fmaxf(m1, __shfl_xor_sync(0xffffffffu, m1, 2));
    float sum0 = 0.f, sum1 = 0.f;
#pragma unroll
    for (int nt = 0; nt < 16; nt++) {
        acc[nt][0] = __expf(acc[nt][0] - m0); sum0 += acc[nt][0];
        acc[nt][1] = __expf(acc[nt][1] - m0); sum0 += acc[nt][1];
        acc[nt][2] = __expf(acc[nt][2] - m1); sum1 += acc[nt][2];
        acc[nt][3] = __expf(acc[nt][3] - m1); sum1 += acc[nt][3];
    }
    sum0 += __shfl_xor_sync(0xffffffffu, sum0, 1);
    sum0 += __shfl_xor_sync(0xffffffffu, sum0, 2);
    sum1 += __shfl_xor_sync(0xffffffffu, sum1, 1);
    sum1 += __shfl_xor_sync(0xffffffffu, sum1, 2);
    const float inv0 = 1.f / sum0, inv1 = 1.f / sum1;

    // ---- repack P into A-fragments (C-frag layout == A-frag layout) ----
    uint32_t ph[8][4], pl[8][4];
#pragma unroll
    for (int c = 0; c < 8; c++) {
        packsplit2(acc[2*c][0]   * inv0, acc[2*c][1]   * inv0, ph[c][0], pl[c][0]);
        packsplit2(acc[2*c][2]   * inv1, acc[2*c][3]   * inv1, ph[c][1], pl[c][1]);
        packsplit2(acc[2*c+1][0] * inv0, acc[2*c+1][1] * inv0, ph[c][2], pl[c][2]);
        packsplit2(acc[2*c+1][2] * inv1, acc[2*c+1][3] * inv1, ph[c][3], pl[c][3]);
    }
#pragma unroll
    for (int i = 0; i < 16; i++)
#pragma unroll
        for (int j = 0; j < 4; j++) acc[i][j] = 0.f;

    // ---- Phase 3: out = P * V (8 k-chunks) ----
    for (int v = 0; v < 8; v++) {
        CPWAIT2();
        __syncthreads();
        if (v + 3 < 8) loadV(v + 3);
        CPCOMMIT();

        const uint32_t ks = sb + ATT_KST + (uint32_t)((v & 3) * 8704);
#pragma unroll
        for (int gp = 0; gp < 4; gp++) {
            uint32_t b0h[4], b0l[4], b1h[4], b1l[4];
            uint32_t a0 = ks + kr * 272 + ((2 * gp) * 16 + nf) * 2;
            uint32_t a1 = ks + kr * 272 + ((2 * gp + 1) * 16 + nf) * 2;
            ldsm4t(b0h, a0); ldsm4t(b0l, a0 + 4352);
            ldsm4t(b1h, a1); ldsm4t(b1l, a1 + 4352);
            float* c0 = acc[4 * gp],     *c1 = acc[4 * gp + 1];
            float* c2 = acc[4 * gp + 2], *c3 = acc[4 * gp + 3];
            mma_bf16(c0, ph[v], b0h);  mma_bf16(c1, ph[v], b0h + 2);
            mma_bf16(c2, ph[v], b1h);  mma_bf16(c3, ph[v], b1h + 2);
            mma_bf16(c0, pl[v], b0h);  mma_bf16(c1, pl[v], b0h + 2);
            mma_bf16(c2, pl[v], b1h);  mma_bf16(c3, pl[v], b1h + 2);
            mma_bf16(c0, ph[v], b0l);  mma_bf16(c1, ph[v], b0l + 2);
            mma_bf16(c2, ph[v], b1l);  mma_bf16(c3, ph[v], b1l + 2);
        }
    }

    // ---- write att as tf32-rounded f32 plane ----
    {
        const int g = lane >> 2, c2 = (lane & 3) * 2;
        const size_t r0 = bhoff + (size_t)(w * 16 + g) * 128;
#pragma unroll
        for (int nt = 0; nt < 16; nt++) {
            int col = nt * 8 + c2;
            *(float2*)(attf + r0 + col) =
                make_float2(tf32r(acc[nt][0]), tf32r(acc[nt][1]));
            *(float2*)(attf + r0 + 8 * 128 + col) =
                make_float2(tf32r(acc[nt][2]), tf32r(acc[nt][3]));
        }
    }
}

// ======================= launch ==============================================
extern "C" void kernel_launch(void* const* d_in, const int* in_sizes, int n_in,
                              void* d_out, int out_size)
{
    (void)in_sizes; (void)n_in; (void)out_size;
    const float* inp[3] = { (const float*)d_in[0], (const float*)d_in[1],
                            (const float*)d_in[2] };
    const float* W[8] = { (const float*)d_in[3], (const float*)d_in[4],
                          (const float*)d_in[5], (const float*)d_in[6],
                          (const float*)d_in[7], (const float*)d_in[8],
                          (const float*)d_in[9], (const float*)d_in[10] };
    const float* bo = (const float*)d_in[11];
    float* out = (float*)d_out;

    void* symp = nullptr;
    cudaGetSymbolAddress(&symp, g_bf);
    bf16* P = (bf16*)symp;
    float* inf  = (float*)P;                     // 3 f32 planes (6 bf16 units)
    bf16*  ohb  = P + 6ull * PLANE;              // 7 bf16 hi planes
    bf16*  olb  = P + 13ull * PLANE;             // 7 bf16 lo planes
    float* attf = (float*)(P + 20ull * PLANE);   // 1 f32 plane (2 units)
    float* wf   = (float*)(P + 22ull * PLANE);   // 8 f32 weight planes

    cudaFuncSetAttribute(gemm_tf, cudaFuncAttributeMaxDynamicSharedMemorySize, GEMM_SMEM);
    cudaFuncSetAttribute(attn_mma, cudaFuncAttributeMaxDynamicSharedMemorySize, ATT_SMEM);

    // 0) round inputs to tf32 f32 planes
    split_all<<<dim3(16384, 3), 256>>>(inp[0], inp[1], inp[2], inf);

    // 1-2) transpose weights -> tf32 f32 planes [N][K]
    dim3 tgrid(32, 32, 4), tblk(32, 8);
    transpose4<<<tgrid, tblk>>>(W[0], W[1], W[2], W[3], wf);
    transpose4<<<tgrid, tblk>>>(W[4], W[5], W[6], W[7], wf + 4ull * WPLANE_F);

    // 3-5) combined projections (tf32 single pass) -> bf16 hi/lo head planes
    gemm_tf<<<dim3(48, 128), 256, GEMM_SMEM>>>(
        inf, wf, nullptr, ohb, olb, nullptr, 128, 1024, 16384, 128);        // words: q,k,v
    gemm_tf<<<dim3(32, 128), 256, GEMM_SMEM>>>(
        inf + PLANE, wf + 3ull * WPLANE_F,
        nullptr, ohb + 3ull * PLANE, olb + 3ull * PLANE, nullptr,
        128, 1024, 16384, 128);                                             // position: q,k
    gemm_tf<<<dim3(32, 128), 256, GEMM_SMEM>>>(
        inf + 2ull * PLANE, wf + 5ull * WPLANE_F,
        nullptr, ohb + 5ull * PLANE, olb + 5ull * PLANE, nullptr,
        128, 1024, 16384, 128);                                             // conscious: q,k

    // 6) attention (bf16-split) -> tf32 f32 att plane
    attn_mma<<<1024, 256, ATT_SMEM>>>(ohb, olb, attf);

    // 7) final GEMM: att * Wo^T + bias -> f32 out (row-major)
    gemm_tf<<<dim3(16, 128), 256, GEMM_SMEM>>>(
        attf, wf + 7ull * WPLANE_F,
        out, nullptr, nullptr, bo, 16384, 128, 128, 1024);
}

// round 10
// speedup vs baseline: 1.1221x; 1.1221x over previous
#include <cuda_runtime.h>
#include <cuda_bf16.h>
#include <cstdint>

// Problem: B=128, N=128, D=1024, H=8, HD=128, M = B*N = 16384
#define PLANE    (16384ull * 1024ull)   // activation plane elems
#define WPLANE_F (1024ull * 1024ull)    // f32 weight plane elems
__device__ __align__(1024) __nv_bfloat16 g_bf[22ull * PLANE + 32ull * WPLANE_F];

typedef __nv_bfloat16 bf16;

// ======================= PTX helpers =========================================
__device__ __forceinline__ uint32_t s2u(const void* p) {
    uint32_t a;
    asm("{ .reg .u64 t; cvta.to.shared.u64 t, %1; cvt.u32.u64 %0, t; }"
        : "=r"(a) : "l"(p));
    return a;
}
__device__ __forceinline__ void ldsm4(uint32_t* r, uint32_t addr) {
    asm volatile("ldmatrix.sync.aligned.m8n8.x4.shared.b16 {%0,%1,%2,%3}, [%4];"
                 : "=r"(r[0]), "=r"(r[1]), "=r"(r[2]), "=r"(r[3]) : "r"(addr));
}
__device__ __forceinline__ void ldsm4t(uint32_t* r, uint32_t addr) {
    asm volatile("ldmatrix.sync.aligned.m8n8.x4.trans.shared.b16 {%0,%1,%2,%3}, [%4];"
                 : "=r"(r[0]), "=r"(r[1]), "=r"(r[2]), "=r"(r[3]) : "r"(addr));
}
__device__ __forceinline__ void mma_bf16(float* d, const uint32_t* a, const uint32_t* b) {
    asm volatile(
        "mma.sync.aligned.m16n8k16.row.col.f32.bf16.bf16.f32 "
        "{%0,%1,%2,%3},{%4,%5,%6,%7},{%8,%9},{%0,%1,%2,%3};"
        : "+f"(d[0]), "+f"(d[1]), "+f"(d[2]), "+f"(d[3])
        : "r"(a[0]), "r"(a[1]), "r"(a[2]), "r"(a[3]), "r"(b[0]), "r"(b[1]));
}
__device__ __forceinline__ void mma_tf32(float* d, const uint32_t* a, const uint32_t* b) {
    asm volatile(
        "mma.sync.aligned.m16n8k8.row.col.f32.tf32.tf32.f32 "
        "{%0,%1,%2,%3},{%4,%5,%6,%7},{%8,%9},{%0,%1,%2,%3};"
        : "+f"(d[0]), "+f"(d[1]), "+f"(d[2]), "+f"(d[3])
        : "r"(a[0]), "r"(a[1]), "r"(a[2]), "r"(a[3]), "r"(b[0]), "r"(b[1]));
}
#define CP16(dst, src) \
    asm volatile("cp.async.cg.shared.global [%0], [%1], 16;" :: "r"(dst), "l"(src))
#define CPCOMMIT() asm volatile("cp.async.commit_group;" ::: "memory")
#define CPWAIT2()  asm volatile("cp.async.wait_group 2;" ::: "memory")
#define CPWAIT0()  asm volatile("cp.async.wait_group 0;" ::: "memory")

__device__ __forceinline__ float tf32r(float x) {   // round-to-nearest tf32
    uint32_t u; asm("cvt.rna.tf32.f32 %0, %1;" : "=r"(u) : "f"(x));
    return __uint_as_float(u);
}
__device__ __forceinline__ void split1(float v, bf16& h, bf16& l) {
    h = __float2bfloat16(v);
    l = __float2bfloat16(v - __bfloat162float(h));
}
__device__ __forceinline__ void packsplit2(float x0, float x1,
                                           uint32_t& hi, uint32_t& lo) {
    bf16 h0, l0, h1, l1;
    split1(x0, h0, l0); split1(x1, h1, l1);
    __nv_bfloat162 hh; hh.x = h0; hh.y = h1;
    __nv_bfloat162 ll; ll.x = l0; ll.y = l1;
    hi = *(uint32_t*)&hh; lo = *(uint32_t*)&ll;
}

// ======================= input rounding (3 inputs -> tf32 f32 planes) ========
__global__ __launch_bounds__(256) void split_all(
    const float* __restrict__ s0, const float* __restrict__ s1,
    const float* __restrict__ s2, float* __restrict__ ob)
{
    const float* src = (blockIdx.y == 0) ? s0 : (blockIdx.y == 1) ? s1 : s2;
    float* o = ob + (size_t)blockIdx.y * PLANE;
    size_t i4 = ((size_t)blockIdx.x * 256 + threadIdx.x) * 4;
    float4 v = *(const float4*)(src + i4);
    v.x = tf32r(v.x); v.y = tf32r(v.y); v.z = tf32r(v.z); v.w = tf32r(v.w);
    *(float4*)(o + i4) = v;
}

// ======================= weight transpose -> tf32 f32 planes (4 each) ========
__global__ __launch_bounds__(256) void transpose4(
    const float* __restrict__ s0, const float* __restrict__ s1,
    const float* __restrict__ s2, const float* __restrict__ s3,
    float* __restrict__ ob)
{
    const float* src = (blockIdx.z == 0) ? s0 : (blockIdx.z == 1) ? s1
                     : (blockIdx.z == 2) ? s2 : s3;
    float* o = ob + (size_t)blockIdx.z * WPLANE_F;
    __shared__ float t[32][33];
    int bx = blockIdx.x * 32, by = blockIdx.y * 32;
    int tx = threadIdx.x, ty = threadIdx.y;
#pragma unroll
    for (int i = ty; i < 32; i += 8)
        t[i][tx] = src[(size_t)(by + i) * 1024 + bx + tx];
    __syncthreads();
#pragma unroll
    for (int i = ty; i < 32; i += 8)
        o[(size_t)(bx + i) * 1024 + by + tx] = tf32r(t[tx][i]);
}

// ======================= single-pass tf32 mma.sync GEMM ======================
// Round-8 geometry: CTA 128x128, 256 thr, warp tile 64x32, 2 CTAs/SM.
// k16 chunks processed in PAIRS: one wait+barrier+commit per pair (32 total).
// smem stage: A@0 (128 x 80B), B@10240 (128 x 80B); stage stride 20480, 4 stages.
// mode=1: merged projections — ct maps to (A plane, W plane, 128-col tile):
//   ct<24: words (ap 0, w ct>>3); ct<40: position (ap 1, w 3+..); else conscious.
// mode=0: single plane (final GEMM), B pre-offset, bct = ct.
#define GEMM_SMEM (4 * 20480)

__global__ __launch_bounds__(256, 2) void gemm_tf(
    const float* __restrict__ A, const float* __restrict__ B,
    float* __restrict__ Cf, bf16* __restrict__ Ch, bf16* __restrict__ Cl,
    const float* __restrict__ bias, int ACB, int ARI, int CCB, int CRI, int mode)
{
    extern __shared__ __align__(1024) char smem[];
    const uint32_t sb = s2u(smem);
    const int tid = threadIdx.x;
    const int lane = tid & 31, wid = tid >> 5;
    const int rt = blockIdx.y, ct = blockIdx.x;

    int ap, bp, bct;
    if (mode) {
        if (ct < 24)      { ap = 0; bp = ct >> 3;              bct = ct & 7; }
        else if (ct < 40) { ap = 1; bp = 3 + ((ct - 24) >> 3); bct = (ct - 24) & 7; }
        else              { ap = 2; bp = 5 + ((ct - 40) >> 3); bct = (ct - 40) & 7; }
    } else { ap = 0; bp = 0; bct = ct; }

    const int wm = wid & 1, wn = wid >> 1;
    const uint32_t aLane = (uint32_t)((lane & 15) * 80 + (lane >> 4) * 16);
    const uint32_t bLane = (uint32_t)(((lane & 7) + (lane >> 4) * 8) * 80
                                      + ((lane >> 3) & 1) * 16);

    const int lrow = tid >> 2, seg = tid & 3;
    const uint32_t dstoff = (uint32_t)(lrow * 80 + seg * 16);
    const float* Abase = A + (size_t)ap * PLANE;
    const float* Bbase = B + (size_t)bp * WPLANE_F;

    float acc[4][4][4];
#pragma unroll
    for (int i = 0; i < 4; i++)
#pragma unroll
        for (int j = 0; j < 4; j++)
#pragma unroll
            for (int k = 0; k < 4; k++) acc[i][j][k] = 0.f;

    auto load_chunk = [&](int c) {
        const int kk = c * 16;
        const uint32_t st = sb + (uint32_t)((c & 3) * 20480) + dstoff;
#pragma unroll
        for (int p = 0; p < 2; p++) {
            const int row = lrow + p * 64;
            const size_t asrc = (size_t)rt * 131072 + (size_t)(kk >> 7) * ACB
                              + (size_t)row * ARI + (kk & 127) + seg * 4;
            CP16(st + (uint32_t)(p * 64 * 80), Abase + asrc);
            const size_t bsrc = (size_t)(bct * 128 + row) * 1024 + kk + seg * 4;
            CP16(st + 10240u + (uint32_t)(p * 64 * 80), Bbase + bsrc);
        }
    };
    auto compute_chunk = [&](int c) {
        const uint32_t off = sb + (uint32_t)((c & 3) * 20480);
        uint32_t bt[2][4][2];
#pragma unroll
        for (int ks = 0; ks < 2; ks++)
#pragma unroll
            for (int pr = 0; pr < 2; pr++) {
                uint32_t q[4];
                ldsm4(q, off + 10240u + (uint32_t)((wn * 32 + pr * 16) * 80)
                         + bLane + (uint32_t)(ks * 32));
                bt[ks][2 * pr][0]     = q[0]; bt[ks][2 * pr][1]     = q[1];
                bt[ks][2 * pr + 1][0] = q[2]; bt[ks][2 * pr + 1][1] = q[3];
            }
#pragma unroll
        for (int ks = 0; ks < 2; ks++) {
            uint32_t at[4][4];
#pragma unroll
            for (int mt = 0; mt < 4; mt++)
                ldsm4(at[mt], off + (uint32_t)((wm * 64 + mt * 16) * 80)
                              + aLane + (uint32_t)(ks * 32));
#pragma unroll
            for (int mt = 0; mt < 4; mt++)
#pragma unroll
                for (int nt = 0; nt < 4; nt++)
                    mma_tf32(acc[mt][nt], at[mt], bt[ks][nt]);
        }
    };

    // prologue: pair 0 in flight
    load_chunk(0); load_chunk(1); CPCOMMIT();

    for (int p = 0; p < 32; p++) {
        CPWAIT0();               // pair p resident (covered by pair p-1 compute)
        __syncthreads();         // all warps done with pair p-1's stages
        if (p + 1 < 32) { load_chunk(2 * p + 2); load_chunk(2 * p + 3); }
        CPCOMMIT();
        compute_chunk(2 * p);
        compute_chunk(2 * p + 1);
    }

    // ---- epilogue ----
    const int g = lane >> 2, cp2 = (lane & 3) * 2;
    const size_t cbase = (size_t)bp * PLANE + (size_t)rt * 131072 + (size_t)bct * CCB;
#pragma unroll
    for (int mt = 0; mt < 4; mt++) {
#pragma unroll
        for (int nt = 0; nt < 4; nt++) {
            int r0 = wm * 64 + mt * 16 + g;
            int col = wn * 32 + nt * 8 + cp2;
            float v0 = acc[mt][nt][0], v1 = acc[mt][nt][1];
            float v2 = acc[mt][nt][2], v3 = acc[mt][nt][3];
            size_t o0 = cbase + (size_t)r0 * CRI + col;
            size_t o1 = cbase + (size_t)(r0 + 8) * CRI + col;
            if (Cf) {
                float b0 = bias[bct * 128 + col], b1 = bias[bct * 128 + col + 1];
                *(float2*)(Cf + o0) = make_float2(v0 + b0, v1 + b1);
                *(float2*)(Cf + o1) = make_float2(v2 + b0, v3 + b1);
            } else {
                uint32_t hh, ll;
                packsplit2(v0, v1, hh, ll);
                *(uint32_t*)(Ch + o0) = hh; *(uint32_t*)(Cl + o0) = ll;
                packsplit2(v2, v3, hh, ll);
                *(uint32_t*)(Ch + o1) = hh; *(uint32_t*)(Cl + o1) = ll;
            }
        }
    }
}

// ======================= mma attention (bf16-split, register-resident P) =====
// One CTA per (b,h). Warp w owns rows w*16..w*16+15 (full 128 cols).
// Output: single f32 plane, tf32-rounded (feeds final tf32 GEMM).
// smem: Q stages@0 (4 x 12288: h@0 l@6144), K/V stages@49152 (4 x 8704).
#define ATT_SMEM 83968
#define ATT_KST  49152u

__global__ __launch_bounds__(256, 1) void attn_mma(
    const bf16* __restrict__ ohb, const bf16* __restrict__ olb,
    float* __restrict__ attf)
{
    extern __shared__ __align__(1024) char smem[];
    const uint32_t sb = s2u(smem);
    const int tid = threadIdx.x;
    const int lane = tid & 31, w = tid >> 5;
    const size_t bhoff = (size_t)blockIdx.x * 16384;

    // plane order in ohb: 0 qw, 1 kw, 2 vw, 3 qp, 4 kp, 5 qc, 6 kc
    const int qpl[3] = { 0, 3, 5 }, kpl[3] = { 1, 4, 6 };

    const int s8 = lane >> 3, r8 = lane & 7;
    const uint32_t aLane = (uint32_t)(((s8 & 1) * 8 + r8) * 48 + (s8 >> 1) * 16);
    const uint32_t kr = (uint32_t)(lane & 15);
    const uint32_t nf = (uint32_t)((lane >> 4) * 8);
    const uint32_t wrow48 = (uint32_t)(w * 16 * 48);

    const int qrow = tid >> 1, qhalf = tid & 1;
    const uint32_t qdst = (uint32_t)(qrow * 48 + qhalf * 16);
    const int krow = tid >> 4, kseg = tid & 15;
    const uint32_t kdst = (uint32_t)(krow * 272 + kseg * 16);

    auto loadQK = [&](int it) {
        int s = it >> 3, c = it & 7;
        uint32_t qs = sb + (uint32_t)((it & 3) * 12288) + qdst;
        size_t qsrc = (size_t)qpl[s] * PLANE + bhoff + (size_t)qrow * 128 + c * 16 + qhalf * 8;
        CP16(qs,        ohb + qsrc);
        CP16(qs + 6144, olb + qsrc);
        uint32_t ks = sb + ATT_KST + (uint32_t)((it & 3) * 8704) + kdst;
        size_t ksrc = (size_t)kpl[s] * PLANE + bhoff + (size_t)(c * 16 + krow) * 128 + kseg * 8;
        CP16(ks,        ohb + ksrc);
        CP16(ks + 4352, olb + ksrc);
    };
    auto loadV = [&](int v) {
        uint32_t ks = sb + ATT_KST + (uint32_t)((v & 3) * 8704) + kdst;
        size_t ksrc = 2ull * PLANE + bhoff + (size_t)(v * 16 + krow) * 128 + kseg * 8;
        CP16(ks,        ohb + ksrc);
        CP16(ks + 4352, olb + ksrc);
    };

    float acc[16][4];
#pragma unroll
    for (int i = 0; i < 16; i++)
#pragma unroll
        for (int j = 0; j < 4; j++) acc[i][j] = 0.f;

    loadQK(0); CPCOMMIT();
    loadQK(1); CPCOMMIT();
    loadQK(2); CPCOMMIT();

    // ---- Phase 1: sim (24 iters = 3 streams x 8 k-chunks) ----
    for (int it = 0; it < 24; it++) {
        CPWAIT2();
        __syncthreads();
        if (it + 3 < 24) loadQK(it + 3);
        CPCOMMIT();

        const uint32_t qs = sb + (uint32_t)((it & 3) * 12288);
        const uint32_t ks = sb + ATT_KST + (uint32_t)((it & 3) * 8704);
        uint32_t ah[4], al[4];
        ldsm4(ah, qs + wrow48 + aLane);
        ldsm4(al, qs + 6144 + wrow48 + aLane);
#pragma unroll
        for (int gp = 0; gp < 4; gp++) {
            uint32_t b0h[4], b0l[4], b1h[4], b1l[4];
            uint32_t a0 = ks + kr * 272 + ((2 * gp) * 16 + nf) * 2;
            uint32_t a1 = ks + kr * 272 + ((2 * gp + 1) * 16 + nf) * 2;
            ldsm4t(b0h, a0); ldsm4t(b0l, a0 + 4352);
            ldsm4t(b1h, a1); ldsm4t(b1l, a1 + 4352);
            float* c0 = acc[4 * gp],     *c1 = acc[4 * gp + 1];
            float* c2 = acc[4 * gp + 2], *c3 = acc[4 * gp + 3];
            mma_bf16(c0, ah, b0h);     mma_bf16(c1, ah, b0h + 2);
            mma_bf16(c2, ah, b1h);     mma_bf16(c3, ah, b1h + 2);
            mma_bf16(c0, al, b0h);     mma_bf16(c1, al, b0h + 2);
            mma_bf16(c2, al, b1h);     mma_bf16(c3, al, b1h + 2);
            mma_bf16(c0, ah, b0l);     mma_bf16(c1, ah, b0l + 2);
            mma_bf16(c2, ah, b1l);     mma_bf16(c3, ah, b1l + 2);
        }
    }

    // drain QK traffic, then prefetch V into stages 0..2 (overlaps softmax)
    CPWAIT0();
    __syncthreads();
    loadV(0); CPCOMMIT();
    loadV(1); CPCOMMIT();
    loadV(2); CPCOMMIT();

    // ---- Phase 2: softmax (warp-local; lane rows g and g+8) ----
    const float SC = 0.08838834764831845f;   // 128^-0.5
    float m0 = -1e30f, m1 = -1e30f;
#pragma unroll
    for (int nt = 0; nt < 16; nt++) {
#pragma unroll
        for (int j = 0; j < 4; j++) acc[nt][j] *= SC;
        m0 = fmaxf(m0, fmaxf(acc[nt][0], acc[nt][1]));
        m1 = fmaxf(m1, fmaxf(acc[nt][2], acc[nt][3]));
    }
    m0 = fmaxf(m0, __shfl_xor_sync(0xffffffffu, m0, 1));
    m0 = fmaxf(m0, __shfl_xor_sync(0xffffffffu, m0, 2));
    m1 = fmaxf(m1, __shfl_xor_sync(0xffffffffu, m1, 1));
    m1 = fmaxf(m1, __shfl_xor_sync(0xffffffffu, m1, 2));
    float sum0 = 0.f, sum1 = 0.f;
#pragma unroll
    for (int nt = 0; nt < 16; nt++) {
        acc[nt][0] = __expf(acc[nt][0] - m0); sum0 += acc[nt][0];
        acc[nt][1] = __expf(acc[nt][1] - m0); sum0 += acc[nt][1];
        acc[nt][2] = __expf(acc[nt][2] - m1); sum1 += acc[nt][2];
        acc[nt][3] = __expf(acc[nt][3] - m1); sum1 += acc[nt][3];
    }
    sum0 += __shfl_xor_sync(0xffffffffu, sum0, 1);
    sum0 += __shfl_xor_sync(0xffffffffu, sum0, 2);
    sum1 += __shfl_xor_sync(0xffffffffu, sum1, 1);
    sum1 += __shfl_xor_sync(0xffffffffu, sum1, 2);
    const float inv0 = 1.f / sum0, inv1 = 1.f / sum1;

    // ---- repack P into A-fragments (C-frag layout == A-frag layout) ----
    uint32_t ph[8][4], pl[8][4];
#pragma unroll
    for (int c = 0; c < 8; c++) {
        packsplit2(acc[2*c][0]   * inv0, acc[2*c][1]   * inv0, ph[c][0], pl[c][0]);
        packsplit2(acc[2*c][2]   * inv1, acc[2*c][3]   * inv1, ph[c][1], pl[c][1]);
        packsplit2(acc[2*c+1][0] * inv0, acc[2*c+1][1] * inv0, ph[c][2], pl[c][2]);
        packsplit2(acc[2*c+1][2] * inv1, acc[2*c+1][3] * inv1, ph[c][3], pl[c][3]);
    }
#pragma unroll
    for (int i = 0; i < 16; i++)
#pragma unroll
        for (int j = 0; j < 4; j++) acc[i][j] = 0.f;

    // ---- Phase 3: out = P * V (8 k-chunks) ----
    for (int v = 0; v < 8; v++) {
        CPWAIT2();
        __syncthreads();
        if (v + 3 < 8) loadV(v + 3);
        CPCOMMIT();

        const uint32_t ks = sb + ATT_KST + (uint32_t)((v & 3) * 8704);
#pragma unroll
        for (int gp = 0; gp < 4; gp++) {
            uint32_t b0h[4], b0l[4], b1h[4], b1l[4];
            uint32_t a0 = ks + kr * 272 + ((2 * gp) * 16 + nf) * 2;
            uint32_t a1 = ks + kr * 272 + ((2 * gp + 1) * 16 + nf) * 2;
            ldsm4t(b0h, a0); ldsm4t(b0l, a0 + 4352);
            ldsm4t(b1h, a1); ldsm4t(b1l, a1 + 4352);
            float* c0 = acc[4 * gp],     *c1 = acc[4 * gp + 1];
            float* c2 = acc[4 * gp + 2], *c3 = acc[4 * gp + 3];
            mma_bf16(c0, ph[v], b0h);  mma_bf16(c1, ph[v], b0h + 2);
            mma_bf16(c2, ph[v], b1h);  mma_bf16(c3, ph[v], b1h + 2);
            mma_bf16(c0, pl[v], b0h);  mma_bf16(c1, pl[v], b0h + 2);
            mma_bf16(c2, pl[v], b1h);  mma_bf16(c3, pl[v], b1h + 2);
            mma_bf16(c0, ph[v], b0l);  mma_bf16(c1, ph[v], b0l + 2);
            mma_bf16(c2, ph[v], b1l);  mma_bf16(c3, ph[v], b1l + 2);
        }
    }

    // ---- write att as tf32-rounded f32 plane ----
    {
        const int g = lane >> 2, c2 = (lane & 3) * 2;
        const size_t r0 = bhoff + (size_t)(w * 16 + g) * 128;
#pragma unroll
        for (int nt = 0; nt < 16; nt++) {
            int col = nt * 8 + c2;
            *(float2*)(attf + r0 + col) =
                make_float2(tf32r(acc[nt][0]), tf32r(acc[nt][1]));
            *(float2*)(attf + r0 + 8 * 128 + col) =
                make_float2(tf32r(acc[nt][2]), tf32r(acc[nt][3]));
        }
    }
}

// ======================= launch ==============================================
extern "C" void kernel_launch(void* const* d_in, const int* in_sizes, int n_in,
                              void* d_out, int out_size)
{
    (void)in_sizes; (void)n_in; (void)out_size;
    const float* inp[3] = { (const float*)d_in[0], (const float*)d_in[1],
                            (const float*)d_in[2] };
    const float* W[8] = { (const float*)d_in[3], (const float*)d_in[4],
                          (const float*)d_in[5], (const float*)d_in[6],
                          (const float*)d_in[7], (const float*)d_in[8],
                          (const float*)d_in[9], (const float*)d_in[10] };
    const float* bo = (const float*)d_in[11];
    float* out = (float*)d_out;

    void* symp = nullptr;
    cudaGetSymbolAddress(&symp, g_bf);
    bf16* P = (bf16*)symp;
    float* inf  = (float*)P;                     // 3 f32 planes (6 bf16 units)
    bf16*  ohb  = P + 6ull * PLANE;              // 7 bf16 hi planes
    bf16*  olb  = P + 13ull * PLANE;             // 7 bf16 lo planes
    float* attf = (float*)(P + 20ull * PLANE);   // 1 f32 plane (2 units)
    float* wf   = (float*)(P + 22ull * PLANE);   // 8 f32 weight planes

    cudaFuncSetAttribute(gemm_tf, cudaFuncAttributeMaxDynamicSharedMemorySize, GEMM_SMEM);
    cudaFuncSetAttribute(attn_mma, cudaFuncAttributeMaxDynamicSharedMemorySize, ATT_SMEM);

    // 0) round inputs to tf32 f32 planes
    split_all<<<dim3(16384, 3), 256>>>(inp[0], inp[1], inp[2], inf);

    // 1-2) transpose weights -> tf32 f32 planes [N][K]
    dim3 tgrid(32, 32, 4), tblk(32, 8);
    transpose4<<<tgrid, tblk>>>(W[0], W[1], W[2], W[3], wf);
    transpose4<<<tgrid, tblk>>>(W[4], W[5], W[6], W[7], wf + 4ull * WPLANE_F);

    // 3) ALL projections in one launch (merged ct mapping) -> bf16 hi/lo planes
    gemm_tf<<<dim3(56, 128), 256, GEMM_SMEM>>>(
        inf, wf, nullptr, ohb, olb, nullptr, 128, 1024, 16384, 128, 1);

    // 4) attention (bf16-split) -> tf32 f32 att plane
    attn_mma<<<1024, 256, ATT_SMEM>>>(ohb, olb, attf);

    // 5) final GEMM: att * Wo^T + bias -> f32 out (row-major)
    gemm_tf<<<dim3(8, 128), 256, GEMM_SMEM>>>(
        attf, wf + 7ull * WPLANE_F,
        out, nullptr, nullptr, bo, 16384, 128, 128, 1024, 0);
}

// round 11
// speedup vs baseline: 1.5984x; 1.4246x over previous
#include <cuda_runtime.h>
#include <cuda_bf16.h>
#include <cuda_fp16.h>
#include <cstdint>

// Problem: B=128, N=128, D=1024, H=8, HD=128, M = B*N = 16384
#define PLANE    (16384ull * 1024ull)   // activation plane elems (2B units)
#define WPLANE   (1024ull * 1024ull)    // weight plane elems
__device__ __align__(1024) __nv_bfloat16 g_bf[22ull * PLANE + 32ull * WPLANE];

typedef __nv_bfloat16 bf16;

// ======================= PTX helpers =========================================
__device__ __forceinline__ uint32_t s2u(const void* p) {
    uint32_t a;
    asm("{ .reg .u64 t; cvta.to.shared.u64 t, %1; cvt.u32.u64 %0, t; }"
        : "=r"(a) : "l"(p));
    return a;
}
__device__ __forceinline__ void ldsm4(uint32_t* r, uint32_t addr) {
    asm volatile("ldmatrix.sync.aligned.m8n8.x4.shared.b16 {%0,%1,%2,%3}, [%4];"
                 : "=r"(r[0]), "=r"(r[1]), "=r"(r[2]), "=r"(r[3]) : "r"(addr));
}
__device__ __forceinline__ void ldsm4t(uint32_t* r, uint32_t addr) {
    asm volatile("ldmatrix.sync.aligned.m8n8.x4.trans.shared.b16 {%0,%1,%2,%3}, [%4];"
                 : "=r"(r[0]), "=r"(r[1]), "=r"(r[2]), "=r"(r[3]) : "r"(addr));
}
__device__ __forceinline__ void mma_bf16(float* d, const uint32_t* a, const uint32_t* b) {
    asm volatile(
        "mma.sync.aligned.m16n8k16.row.col.f32.bf16.bf16.f32 "
        "{%0,%1,%2,%3},{%4,%5,%6,%7},{%8,%9},{%0,%1,%2,%3};"
        : "+f"(d[0]), "+f"(d[1]), "+f"(d[2]), "+f"(d[3])
        : "r"(a[0]), "r"(a[1]), "r"(a[2]), "r"(a[3]), "r"(b[0]), "r"(b[1]));
}
__device__ __forceinline__ void mma_fp16(float* d, const uint32_t* a, const uint32_t* b) {
    asm volatile(
        "mma.sync.aligned.m16n8k16.row.col.f32.f16.f16.f32 "
        "{%0,%1,%2,%3},{%4,%5,%6,%7},{%8,%9},{%0,%1,%2,%3};"
        : "+f"(d[0]), "+f"(d[1]), "+f"(d[2]), "+f"(d[3])
        : "r"(a[0]), "r"(a[1]), "r"(a[2]), "r"(a[3]), "r"(b[0]), "r"(b[1]));
}
#define CP16(dst, src) \
    asm volatile("cp.async.cg.shared.global [%0], [%1], 16;" :: "r"(dst), "l"(src))
#define CPCOMMIT() asm volatile("cp.async.commit_group;" ::: "memory")
#define CPWAIT2()  asm volatile("cp.async.wait_group 2;" ::: "memory")
#define CPWAIT0()  asm volatile("cp.async.wait_group 0;" ::: "memory")

__device__ __forceinline__ void split1(float v, bf16& h, bf16& l) {
    h = __float2bfloat16(v);
    l = __float2bfloat16(v - __bfloat162float(h));
}
__device__ __forceinline__ void packsplit2(float x0, float x1,
                                           uint32_t& hi, uint32_t& lo) {
    bf16 h0, l0, h1, l1;
    split1(x0, h0, l0); split1(x1, h1, l1);
    __nv_bfloat162 hh; hh.x = h0; hh.y = h1;
    __nv_bfloat162 ll; ll.x = l0; ll.y = l1;
    hi = *(uint32_t*)&hh; lo = *(uint32_t*)&ll;
}
__device__ __forceinline__ uint32_t packh2(float x0, float x1) {
    __half2 h; h.x = __float2half_rn(x0); h.y = __float2half_rn(x1);
    return *(uint32_t*)&h;
}

// ======================= input conversion (3 inputs -> fp16 planes) ==========
__global__ __launch_bounds__(256) void split_all(
    const float* __restrict__ s0, const float* __restrict__ s1,
    const float* __restrict__ s2, __half* __restrict__ ob)
{
    const float* src = (blockIdx.y == 0) ? s0 : (blockIdx.y == 1) ? s1 : s2;
    __half* o = ob + (size_t)blockIdx.y * PLANE;
    size_t i4 = ((size_t)blockIdx.x * 256 + threadIdx.x) * 4;
    float4 v = *(const float4*)(src + i4);
    *(uint32_t*)(o + i4)     = packh2(v.x, v.y);
    *(uint32_t*)(o + i4 + 2) = packh2(v.z, v.w);
}

// ======================= weight transpose -> fp16 planes (4 each) ============
__global__ __launch_bounds__(256) void transpose4(
    const float* __restrict__ s0, const float* __restrict__ s1,
    const float* __restrict__ s2, const float* __restrict__ s3,
    __half* __restrict__ ob)
{
    const float* src = (blockIdx.z == 0) ? s0 : (blockIdx.z == 1) ? s1
                     : (blockIdx.z == 2) ? s2 : s3;
    __half* o = ob + (size_t)blockIdx.z * WPLANE;
    __shared__ float t[32][33];
    int bx = blockIdx.x * 32, by = blockIdx.y * 32;
    int tx = threadIdx.x, ty = threadIdx.y;
#pragma unroll
    for (int i = ty; i < 32; i += 8)
        t[i][tx] = src[(size_t)(by + i) * 1024 + bx + tx];
    __syncthreads();
#pragma unroll
    for (int i = ty; i < 32; i += 8)
        o[(size_t)(bx + i) * 1024 + by + tx] = __float2half_rn(t[tx][i]);
}

// ======================= single-pass fp16 mma.sync GEMM ======================
// CTA 128x128, 256 thr, warp tile 64x32 (2x4 warp grid), 2 CTAs/SM.
// fp16 m16n8k16: 16 MMA + 6 ldsm per k16 chunk. Pair-barrier scheme:
// one wait0+sync+commit per k16 PAIR (32 total). 4-stage ring.
// smem stage: A@0 (128 rows x 48B), B@6144 (128 x 48B); stage stride 12288.
// A idx(r,k) = (r/128)*131072 + (k/128)*ACB + (r%128)*ARI + (k%128)   [halves]
// mode=1: merged projections — ct -> (A plane ap, W plane bp, col tile bct):
//   ct<24: words; ct<40: position; else conscious.
// mode=0: single planes (final GEMM), bct = ct.
#define GEMM_SMEM (4 * 12288)

__global__ __launch_bounds__(256, 2) void gemm_fp(
    const __half* __restrict__ A, const __half* __restrict__ B,
    float* __restrict__ Cf, bf16* __restrict__ Ch, bf16* __restrict__ Cl,
    const float* __restrict__ bias, int ACB, int ARI, int CCB, int CRI, int mode)
{
    extern __shared__ __align__(1024) char smem[];
    const uint32_t sb = s2u(smem);
    const int tid = threadIdx.x;
    const int lane = tid & 31, wid = tid >> 5;
    const int rt = blockIdx.y, ct = blockIdx.x;

    int ap, bp, bct;
    if (mode) {
        if (ct < 24)      { ap = 0; bp = ct >> 3;              bct = ct & 7; }
        else if (ct < 40) { ap = 1; bp = 3 + ((ct - 24) >> 3); bct = (ct - 24) & 7; }
        else              { ap = 2; bp = 5 + ((ct - 40) >> 3); bct = (ct - 40) & 7; }
    } else { ap = 0; bp = 0; bct = ct; }

    const int wm = wid & 1, wn = wid >> 1;
    const int s8 = lane >> 3, r8 = lane & 7;
    const uint32_t aLane = (uint32_t)(((s8 & 1) * 8 + r8) * 48 + (s8 >> 1) * 16);
    const uint32_t bLane = (uint32_t)(((s8 >> 1) * 8 + r8) * 48 + (s8 & 1) * 16);

    const int lrow = tid >> 1, lhalf = tid & 1;
    const uint32_t dstoff = (uint32_t)(lrow * 48 + lhalf * 16);
    const __half* Abase = A + (size_t)ap * PLANE;
    const __half* Bbase = B + (size_t)bp * WPLANE;

    float acc[4][4][4];
#pragma unroll
    for (int i = 0; i < 4; i++)
#pragma unroll
        for (int j = 0; j < 4; j++)
#pragma unroll
            for (int k = 0; k < 4; k++) acc[i][j][k] = 0.f;

    auto load_chunk = [&](int c) {
        const int kk = c * 16;
        const uint32_t st = sb + (uint32_t)((c & 3) * 12288) + dstoff;
        const size_t asrc = (size_t)rt * 131072 + (size_t)(kk >> 7) * ACB
                          + (size_t)lrow * ARI + (kk & 127) + lhalf * 8;
        CP16(st, Abase + asrc);
        const size_t bsrc = (size_t)(bct * 128 + lrow) * 1024 + kk + lhalf * 8;
        CP16(st + 6144u, Bbase + bsrc);
    };
    auto compute_chunk = [&](int c) {
        const uint32_t off = sb + (uint32_t)((c & 3) * 12288);
        uint32_t bt[4][2];
#pragma unroll
        for (int pr = 0; pr < 2; pr++) {
            uint32_t q[4];
            ldsm4(q, off + 6144u + (uint32_t)((wn * 32 + pr * 16) * 48) + bLane);
            bt[2 * pr][0]     = q[0]; bt[2 * pr][1]     = q[1];
            bt[2 * pr + 1][0] = q[2]; bt[2 * pr + 1][1] = q[3];
        }
        uint32_t at[4][4];
#pragma unroll
        for (int mt = 0; mt < 4; mt++)
            ldsm4(at[mt], off + (uint32_t)((wm * 64 + mt * 16) * 48) + aLane);
#pragma unroll
        for (int mt = 0; mt < 4; mt++)
#pragma unroll
            for (int nt = 0; nt < 4; nt++)
                mma_fp16(acc[mt][nt], at[mt], bt[nt]);
    };

    // prologue: pair 0 in flight
    load_chunk(0); load_chunk(1); CPCOMMIT();

    for (int p = 0; p < 32; p++) {
        CPWAIT0();               // pair p resident (covered by pair p-1 compute)
        __syncthreads();
        if (p + 1 < 32) { load_chunk(2 * p + 2); load_chunk(2 * p + 3); }
        CPCOMMIT();
        compute_chunk(2 * p);
        compute_chunk(2 * p + 1);
    }

    // ---- epilogue ----
    const int g = lane >> 2, cp2 = (lane & 3) * 2;
    const size_t cbase = (size_t)bp * PLANE + (size_t)rt * 131072 + (size_t)bct * CCB;
#pragma unroll
    for (int mt = 0; mt < 4; mt++) {
#pragma unroll
        for (int nt = 0; nt < 4; nt++) {
            int r0 = wm * 64 + mt * 16 + g;
            int col = wn * 32 + nt * 8 + cp2;
            float v0 = acc[mt][nt][0], v1 = acc[mt][nt][1];
            float v2 = acc[mt][nt][2], v3 = acc[mt][nt][3];
            size_t o0 = cbase + (size_t)r0 * CRI + col;
            size_t o1 = cbase + (size_t)(r0 + 8) * CRI + col;
            if (Cf) {
                float b0 = bias[bct * 128 + col], b1 = bias[bct * 128 + col + 1];
                *(float2*)(Cf + o0) = make_float2(v0 + b0, v1 + b1);
                *(float2*)(Cf + o1) = make_float2(v2 + b0, v3 + b1);
            } else {
                uint32_t hh, ll;
                packsplit2(v0, v1, hh, ll);
                *(uint32_t*)(Ch + o0) = hh; *(uint32_t*)(Cl + o0) = ll;
                packsplit2(v2, v3, hh, ll);
                *(uint32_t*)(Ch + o1) = hh; *(uint32_t*)(Cl + o1) = ll;
            }
        }
    }
}

// ======================= mma attention (bf16-split, register-resident P) =====
// One CTA per (b,h). Warp w owns rows w*16..w*16+15 (full 128 cols).
// Output: single fp16 plane (feeds final fp16 GEMM).
// smem: Q stages@0 (4 x 12288: h@0 l@6144), K/V stages@49152 (4 x 8704).
#define ATT_SMEM 83968
#define ATT_KST  49152u

__global__ __launch_bounds__(256, 1) void attn_mma(
    const bf16* __restrict__ ohb, const bf16* __restrict__ olb,
    __half* __restrict__ atth)
{
    extern __shared__ __align__(1024) char smem[];
    const uint32_t sb = s2u(smem);
    const int tid = threadIdx.x;
    const int lane = tid & 31, w = tid >> 5;
    const size_t bhoff = (size_t)blockIdx.x * 16384;

    // plane order in ohb: 0 qw, 1 kw, 2 vw, 3 qp, 4 kp, 5 qc, 6 kc
    const int qpl[3] = { 0, 3, 5 }, kpl[3] = { 1, 4, 6 };

    const int s8 = lane >> 3, r8 = lane & 7;
    const uint32_t aLane = (uint32_t)(((s8 & 1) * 8 + r8) * 48 + (s8 >> 1) * 16);
    const uint32_t kr = (uint32_t)(lane & 15);
    const uint32_t nf = (uint32_t)((lane >> 4) * 8);
    const uint32_t wrow48 = (uint32_t)(w * 16 * 48);

    const int qrow = tid >> 1, qhalf = tid & 1;
    const uint32_t qdst = (uint32_t)(qrow * 48 + qhalf * 16);
    const int krow = tid >> 4, kseg = tid & 15;
    const uint32_t kdst = (uint32_t)(krow * 272 + kseg * 16);

    auto loadQK = [&](int it) {
        int s = it >> 3, c = it & 7;
        uint32_t qs = sb + (uint32_t)((it & 3) * 12288) + qdst;
        size_t qsrc = (size_t)qpl[s] * PLANE + bhoff + (size_t)qrow * 128 + c * 16 + qhalf * 8;
        CP16(qs,        ohb + qsrc);
        CP16(qs + 6144, olb + qsrc);
        uint32_t ks = sb + ATT_KST + (uint32_t)((it & 3) * 8704) + kdst;
        size_t ksrc = (size_t)kpl[s] * PLANE + bhoff + (size_t)(c * 16 + krow) * 128 + kseg * 8;
        CP16(ks,        ohb + ksrc);
        CP16(ks + 4352, olb + ksrc);
    };
    auto loadV = [&](int v) {
        uint32_t ks = sb + ATT_KST + (uint32_t)((v & 3) * 8704) + kdst;
        size_t ksrc = 2ull * PLANE + bhoff + (size_t)(v * 16 + krow) * 128 + kseg * 8;
        CP16(ks,        ohb + ksrc);
        CP16(ks + 4352, olb + ksrc);
    };

    float acc[16][4];
#pragma unroll
    for (int i = 0; i < 16; i++)
#pragma unroll
        for (int j = 0; j < 4; j++) acc[i][j] = 0.f;

    loadQK(0); CPCOMMIT();
    loadQK(1); CPCOMMIT();
    loadQK(2); CPCOMMIT();

    // ---- Phase 1: sim (24 iters = 3 streams x 8 k-chunks) ----
    for (int it = 0; it < 24; it++) {
        CPWAIT2();
        __syncthreads();
        if (it + 3 < 24) loadQK(it + 3);
        CPCOMMIT();

        const uint32_t qs = sb + (uint32_t)((it & 3) * 12288);
        const uint32_t ks = sb + ATT_KST + (uint32_t)((it & 3) * 8704);
        uint32_t ah[4], al[4];
        ldsm4(ah, qs + wrow48 + aLane);
        ldsm4(al, qs + 6144 + wrow48 + aLane);
#pragma unroll
        for (int gp = 0; gp < 4; gp++) {
            uint32_t b0h[4], b0l[4], b1h[4], b1l[4];
            uint32_t a0 = ks + kr * 272 + ((2 * gp) * 16 + nf) * 2;
            uint32_t a1 = ks + kr * 272 + ((2 * gp + 1) * 16 + nf) * 2;
            ldsm4t(b0h, a0); ldsm4t(b0l, a0 + 4352);
            ldsm4t(b1h, a1); ldsm4t(b1l, a1 + 4352);
            float* c0 = acc[4 * gp],     *c1 = acc[4 * gp + 1];
            float* c2 = acc[4 * gp + 2], *c3 = acc[4 * gp + 3];
            mma_bf16(c0, ah, b0h);     mma_bf16(c1, ah, b0h + 2);
            mma_bf16(c2, ah, b1h);     mma_bf16(c3, ah, b1h + 2);
            mma_bf16(c0, al, b0h);     mma_bf16(c1, al, b0h + 2);
            mma_bf16(c2, al, b1h);     mma_bf16(c3, al, b1h + 2);
            mma_bf16(c0, ah, b0l);     mma_bf16(c1, ah, b0l + 2);
            mma_bf16(c2, ah, b1l);     mma_bf16(c3, ah, b1l + 2);
        }
    }

    // drain QK traffic, then prefetch V into stages 0..2 (overlaps softmax)
    CPWAIT0();
    __syncthreads();
    loadV(0); CPCOMMIT();
    loadV(1); CPCOMMIT();
    loadV(2); CPCOMMIT();

    // ---- Phase 2: softmax (warp-local; lane rows g and g+8) ----
    const float SC = 0.08838834764831845f;   // 128^-0.5
    float m0 = -1e30f, m1 = -1e30f;
#pragma unroll
    for (int nt = 0; nt < 16; nt++) {
#pragma unroll
        for (int j = 0; j < 4; j++) acc[nt][j] *= SC;
        m0 = fmaxf(m0, fmaxf(acc[nt][0], acc[nt][1]));
        m1 = fmaxf(m1, fmaxf(acc[nt][2], acc[nt][3]));
    }
    m0 = fmaxf(m0, __shfl_xor_sync(0xffffffffu, m0, 1));
    m0 = fmaxf(m0, __shfl_xor_sync(0xffffffffu, m0, 2));
    m1 = fmaxf(m1, __shfl_xor_sync(0xffffffffu, m1, 1));
    m1 = fmaxf(m1, __shfl_xor_sync(0xffffffffu, m1, 2));
    float sum0 = 0.f, sum1 = 0.f;
#pragma unroll
    for (int nt = 0; nt < 16; nt++) {
        acc[nt][0] = __expf(acc[nt][0] - m0); sum0 += acc[nt][0];
        acc[nt][1] = __expf(acc[nt][1] - m0); sum0 += acc[nt][1];
        acc[nt][2] = __expf(acc[nt][2] - m1); sum1 += acc[nt][2];
        acc[nt][3] = __expf(acc[nt][3] - m1); sum1 += acc[nt][3];
    }
    sum0 += __shfl_xor_sync(0xffffffffu, sum0, 1);
    sum0 += __shfl_xor_sync(0xffffffffu, sum0, 2);
    sum1 += __shfl_xor_sync(0xffffffffu, sum1, 1);
    sum1 += __shfl_xor_sync(0xffffffffu, sum1, 2);
    const float inv0 = 1.f / sum0, inv1 = 1.f / sum1;

    // ---- repack P into A-fragments (C-frag layout == A-frag layout) ----
    uint32_t ph[8][4], pl[8][4];
#pragma unroll
    for (int c = 0; c < 8; c++) {
        packsplit2(acc[2*c][0]   * inv0, acc[2*c][1]   * inv0, ph[c][0], pl[c][0]);
        packsplit2(acc[2*c][2]   * inv1, acc[2*c][3]   * inv1, ph[c][1], pl[c][1]);
        packsplit2(acc[2*c+1][0] * inv0, acc[2*c+1][1] * inv0, ph[c][2], pl[c][2]);
        packsplit2(acc[2*c+1][2] * inv1, acc[2*c+1][3] * inv1, ph[c][3], pl[c][3]);
    }
#pragma unroll
    for (int i = 0; i < 16; i++)
#pragma unroll
        for (int j = 0; j < 4; j++) acc[i][j] = 0.f;

    // ---- Phase 3: out = P * V (8 k-chunks) ----
    for (int v = 0; v < 8; v++) {
        CPWAIT2();
        __syncthreads();
        if (v + 3 < 8) loadV(v + 3);
        CPCOMMIT();

        const uint32_t ks = sb + ATT_KST + (uint32_t)((v & 3) * 8704);
#pragma unroll
        for (int gp = 0; gp < 4; gp++) {
            uint32_t b0h[4], b0l[4], b1h[4], b1l[4];
            uint32_t a0 = ks + kr * 272 + ((2 * gp) * 16 + nf) * 2;
            uint32_t a1 = ks + kr * 272 + ((2 * gp + 1) * 16 + nf) * 2;
            ldsm4t(b0h, a0); ldsm4t(b0l, a0 + 4352);
            ldsm4t(b1h, a1); ldsm4t(b1l, a1 + 4352);
            float* c0 = acc[4 * gp],     *c1 = acc[4 * gp + 1];
            float* c2 = acc[4 * gp + 2], *c3 = acc[4 * gp + 3];
            mma_bf16(c0, ph[v], b0h);  mma_bf16(c1, ph[v], b0h + 2);
            mma_bf16(c2, ph[v], b1h);  mma_bf16(c3, ph[v], b1h + 2);
            mma_bf16(c0, pl[v], b0h);  mma_bf16(c1, pl[v], b0h + 2);
            mma_bf16(c2, pl[v], b1h);  mma_bf16(c3, pl[v], b1h + 2);
            mma_bf16(c0, ph[v], b0l);  mma_bf16(c1, ph[v], b0l + 2);
            mma_bf16(c2, ph[v], b1l);  mma_bf16(c3, ph[v], b1l + 2);
        }
    }

    // ---- write att as fp16 plane ----
    {
        const int g = lane >> 2, c2 = (lane & 3) * 2;
        const size_t r0 = bhoff + (size_t)(w * 16 + g) * 128;
#pragma unroll
        for (int nt = 0; nt < 16; nt++) {
            int col = nt * 8 + c2;
            *(uint32_t*)(atth + r0 + col) = packh2(acc[nt][0], acc[nt][1]);
            *(uint32_t*)(atth + r0 + 8 * 128 + col) = packh2(acc[nt][2], acc[nt][3]);
        }
    }
}

// ======================= launch ==============================================
extern "C" void kernel_launch(void* const* d_in, const int* in_sizes, int n_in,
                              void* d_out, int out_size)
{
    (void)in_sizes; (void)n_in; (void)out_size;
    const float* inp[3] = { (const float*)d_in[0], (const float*)d_in[1],
                            (const float*)d_in[2] };
    const float* W[8] = { (const float*)d_in[3], (const float*)d_in[4],
                          (const float*)d_in[5], (const float*)d_in[6],
                          (const float*)d_in[7], (const float*)d_in[8],
                          (const float*)d_in[9], (const float*)d_in[10] };
    const float* bo = (const float*)d_in[11];
    float* out = (float*)d_out;

    void* symp = nullptr;
    cudaGetSymbolAddress(&symp, g_bf);
    bf16* P = (bf16*)symp;
    __half* infp = (__half*)P;                   // 3 fp16 input planes [0,3)
    bf16*   ohb  = P + 3ull * PLANE;             // 7 bf16 hi planes   [3,10)
    bf16*   olb  = P + 10ull * PLANE;            // 7 bf16 lo planes   [10,17)
    __half* atth = (__half*)(P + 17ull * PLANE); // 1 fp16 att plane   [17,18)
    __half* wfp  = (__half*)(P + 18ull * PLANE); // 8 fp16 weight planes

    cudaFuncSetAttribute(gemm_fp, cudaFuncAttributeMaxDynamicSharedMemorySize, GEMM_SMEM);
    cudaFuncSetAttribute(attn_mma, cudaFuncAttributeMaxDynamicSharedMemorySize, ATT_SMEM);

    // 0) convert inputs to fp16 planes
    split_all<<<dim3(16384, 3), 256>>>(inp[0], inp[1], inp[2], infp);

    // 1-2) transpose weights -> fp16 planes [N][K]
    dim3 tgrid(32, 32, 4), tblk(32, 8);
    transpose4<<<tgrid, tblk>>>(W[0], W[1], W[2], W[3], wfp);
    transpose4<<<tgrid, tblk>>>(W[4], W[5], W[6], W[7], wfp + 4ull * WPLANE);

    // 3) ALL projections in one launch (fp16 single pass) -> bf16 hi/lo planes
    gemm_fp<<<dim3(56, 128), 256, GEMM_SMEM>>>(
        infp, wfp, nullptr, ohb, olb, nullptr, 128, 1024, 16384, 128, 1);

    // 4) attention (bf16-split) -> fp16 att plane
    attn_mma<<<1024, 256, ATT_SMEM>>>(ohb, olb, atth);

    // 5) final GEMM: att * Wo^T + bias -> f32 out (row-major)
    gemm_fp<<<dim3(8, 128), 256, GEMM_SMEM>>>(
        atth, wfp + 7ull * WPLANE,
        out, nullptr, nullptr, bo, 16384, 128, 128, 1024, 0);
}

// round 12
// speedup vs baseline: 1.9268x; 1.2054x over previous
#include <cuda_runtime.h>
#include <cuda_bf16.h>
#include <cuda_fp16.h>
#include <cstdint>

// Problem: B=128, N=128, D=1024, H=8, HD=128, M = B*N = 16384
#define PLANE    (16384ull * 1024ull)   // activation plane elems (2B units)
#define WPLANE   (1024ull * 1024ull)    // weight plane elems
__device__ __align__(1024) __nv_bfloat16 g_bf[22ull * PLANE + 32ull * WPLANE];

typedef __nv_bfloat16 bf16;

// ======================= PTX helpers =========================================
__device__ __forceinline__ uint32_t s2u(const void* p) {
    uint32_t a;
    asm("{ .reg .u64 t; cvta.to.shared.u64 t, %1; cvt.u32.u64 %0, t; }"
        : "=r"(a) : "l"(p));
    return a;
}
__device__ __forceinline__ void ldsm4(uint32_t* r, uint32_t addr) {
    asm volatile("ldmatrix.sync.aligned.m8n8.x4.shared.b16 {%0,%1,%2,%3}, [%4];"
                 : "=r"(r[0]), "=r"(r[1]), "=r"(r[2]), "=r"(r[3]) : "r"(addr));
}
__device__ __forceinline__ void ldsm4t(uint32_t* r, uint32_t addr) {
    asm volatile("ldmatrix.sync.aligned.m8n8.x4.trans.shared.b16 {%0,%1,%2,%3}, [%4];"
                 : "=r"(r[0]), "=r"(r[1]), "=r"(r[2]), "=r"(r[3]) : "r"(addr));
}
__device__ __forceinline__ void mma_bf16(float* d, const uint32_t* a, const uint32_t* b) {
    asm volatile(
        "mma.sync.aligned.m16n8k16.row.col.f32.bf16.bf16.f32 "
        "{%0,%1,%2,%3},{%4,%5,%6,%7},{%8,%9},{%0,%1,%2,%3};"
        : "+f"(d[0]), "+f"(d[1]), "+f"(d[2]), "+f"(d[3])
        : "r"(a[0]), "r"(a[1]), "r"(a[2]), "r"(a[3]), "r"(b[0]), "r"(b[1]));
}
__device__ __forceinline__ void mma_fp16(float* d, const uint32_t* a, const uint32_t* b) {
    asm volatile(
        "mma.sync.aligned.m16n8k16.row.col.f32.f16.f16.f32 "
        "{%0,%1,%2,%3},{%4,%5,%6,%7},{%8,%9},{%0,%1,%2,%3};"
        : "+f"(d[0]), "+f"(d[1]), "+f"(d[2]), "+f"(d[3])
        : "r"(a[0]), "r"(a[1]), "r"(a[2]), "r"(a[3]), "r"(b[0]), "r"(b[1]));
}
#define CP16(dst, src) \
    asm volatile("cp.async.cg.shared.global [%0], [%1], 16;" :: "r"(dst), "l"(src))
#define CPCOMMIT() asm volatile("cp.async.commit_group;" ::: "memory")
#define CPWAIT4()  asm volatile("cp.async.wait_group 4;" ::: "memory")
#define CPWAIT2()  asm volatile("cp.async.wait_group 2;" ::: "memory")
#define CPWAIT0()  asm volatile("cp.async.wait_group 0;" ::: "memory")

__device__ __forceinline__ void split1(float v, bf16& h, bf16& l) {
    h = __float2bfloat16(v);
    l = __float2bfloat16(v - __bfloat162float(h));
}
__device__ __forceinline__ void packsplit2(float x0, float x1,
                                           uint32_t& hi, uint32_t& lo) {
    bf16 h0, l0, h1, l1;
    split1(x0, h0, l0); split1(x1, h1, l1);
    __nv_bfloat162 hh; hh.x = h0; hh.y = h1;
    __nv_bfloat162 ll; ll.x = l0; ll.y = l1;
    hi = *(uint32_t*)&hh; lo = *(uint32_t*)&ll;
}
__device__ __forceinline__ uint32_t packh2(float x0, float x1) {
    __half2 h; h.x = __float2half_rn(x0); h.y = __float2half_rn(x1);
    return *(uint32_t*)&h;
}

// ======================= input conversion (3 inputs -> fp16 planes) ==========
__global__ __launch_bounds__(256) void split_all(
    const float* __restrict__ s0, const float* __restrict__ s1,
    const float* __restrict__ s2, __half* __restrict__ ob)
{
    const float* src = (blockIdx.y == 0) ? s0 : (blockIdx.y == 1) ? s1 : s2;
    __half* o = ob + (size_t)blockIdx.y * PLANE;
    size_t i4 = ((size_t)blockIdx.x * 256 + threadIdx.x) * 4;
    float4 v = *(const float4*)(src + i4);
    *(uint32_t*)(o + i4)     = packh2(v.x, v.y);
    *(uint32_t*)(o + i4 + 2) = packh2(v.z, v.w);
}

// ======================= weight transpose -> fp16 planes (4 each) ============
__global__ __launch_bounds__(256) void transpose4(
    const float* __restrict__ s0, const float* __restrict__ s1,
    const float* __restrict__ s2, const float* __restrict__ s3,
    __half* __restrict__ ob)
{
    const float* src = (blockIdx.z == 0) ? s0 : (blockIdx.z == 1) ? s1
                     : (blockIdx.z == 2) ? s2 : s3;
    __half* o = ob + (size_t)blockIdx.z * WPLANE;
    __shared__ float t[32][33];
    int bx = blockIdx.x * 32, by = blockIdx.y * 32;
    int tx = threadIdx.x, ty = threadIdx.y;
#pragma unroll
    for (int i = ty; i < 32; i += 8)
        t[i][tx] = src[(size_t)(by + i) * 1024 + bx + tx];
    __syncthreads();
#pragma unroll
    for (int i = ty; i < 32; i += 8)
        o[(size_t)(bx + i) * 1024 + by + tx] = __float2half_rn(t[tx][i]);
}

// ======================= single-pass fp16 mma.sync GEMM ======================
// CTA 128x128, 256 thr, warp tile 64x32 (2x4 warp grid), 2 CTAs/SM.
// fp16 m16n8k16: 16 MMA + 6 ldsm per k16 chunk.
// DEEP pipeline: 6-stage ring, per-chunk commit, wait_group 4 (distance 5):
// load-landing window ~5 chunk-computes >> DRAM latency.
// smem stage: A@0 (128 rows x 48B), B@6144 (128 x 48B); stage stride 12288.
// A idx(r,k) = (r/128)*131072 + (k/128)*ACB + (r%128)*ARI + (k%128)   [halves]
// mode=1: merged projections — ct -> (A plane ap, W plane bp, col tile bct).
// mode=0: single planes (final GEMM), bct = ct.
#define GEMM_STAGES 6
#define GEMM_SMEM (GEMM_STAGES * 12288)

__global__ __launch_bounds__(256, 2) void gemm_fp(
    const __half* __restrict__ A, const __half* __restrict__ B,
    float* __restrict__ Cf, bf16* __restrict__ Ch, bf16* __restrict__ Cl,
    const float* __restrict__ bias, int ACB, int ARI, int CCB, int CRI, int mode)
{
    extern __shared__ __align__(1024) char smem[];
    const uint32_t sb = s2u(smem);
    const int tid = threadIdx.x;
    const int lane = tid & 31, wid = tid >> 5;
    const int rt = blockIdx.y, ct = blockIdx.x;

    int ap, bp, bct;
    if (mode) {
        if (ct < 24)      { ap = 0; bp = ct >> 3;              bct = ct & 7; }
        else if (ct < 40) { ap = 1; bp = 3 + ((ct - 24) >> 3); bct = (ct - 24) & 7; }
        else              { ap = 2; bp = 5 + ((ct - 40) >> 3); bct = (ct - 40) & 7; }
    } else { ap = 0; bp = 0; bct = ct; }

    const int wm = wid & 1, wn = wid >> 1;
    const int s8 = lane >> 3, r8 = lane & 7;
    const uint32_t aLane = (uint32_t)(((s8 & 1) * 8 + r8) * 48 + (s8 >> 1) * 16);
    const uint32_t bLane = (uint32_t)(((s8 >> 1) * 8 + r8) * 48 + (s8 & 1) * 16);

    const int lrow = tid >> 1, lhalf = tid & 1;
    const uint32_t dstoff = (uint32_t)(lrow * 48 + lhalf * 16);
    const __half* Abase = A + (size_t)ap * PLANE;
    const __half* Bbase = B + (size_t)bp * WPLANE;

    float acc[4][4][4];
#pragma unroll
    for (int i = 0; i < 4; i++)
#pragma unroll
        for (int j = 0; j < 4; j++)
#pragma unroll
            for (int k = 0; k < 4; k++) acc[i][j][k] = 0.f;

    auto stage_off = [&](int c) -> uint32_t {
        return (uint32_t)((c % GEMM_STAGES) * 12288);
    };
    auto load_chunk = [&](int c) {
        const int kk = c * 16;
        const uint32_t st = sb + stage_off(c) + dstoff;
        const size_t asrc = (size_t)rt * 131072 + (size_t)(kk >> 7) * ACB
                          + (size_t)lrow * ARI + (kk & 127) + lhalf * 8;
        CP16(st, Abase + asrc);
        const size_t bsrc = (size_t)(bct * 128 + lrow) * 1024 + kk + lhalf * 8;
        CP16(st + 6144u, Bbase + bsrc);
    };
    auto compute_chunk = [&](int c) {
        const uint32_t off = sb + stage_off(c);
        uint32_t bt[4][2];
#pragma unroll
        for (int pr = 0; pr < 2; pr++) {
            uint32_t q[4];
            ldsm4(q, off + 6144u + (uint32_t)((wn * 32 + pr * 16) * 48) + bLane);
            bt[2 * pr][0]     = q[0]; bt[2 * pr][1]     = q[1];
            bt[2 * pr + 1][0] = q[2]; bt[2 * pr + 1][1] = q[3];
        }
        uint32_t at[4][4];
#pragma unroll
        for (int mt = 0; mt < 4; mt++)
            ldsm4(at[mt], off + (uint32_t)((wm * 64 + mt * 16) * 48) + aLane);
#pragma unroll
        for (int mt = 0; mt < 4; mt++)
#pragma unroll
            for (int nt = 0; nt < 4; nt++)
                mma_fp16(acc[mt][nt], at[mt], bt[nt]);
    };

    // prologue: chunks 0..4 in flight (5 groups)
    load_chunk(0); CPCOMMIT();
    load_chunk(1); CPCOMMIT();
    load_chunk(2); CPCOMMIT();
    load_chunk(3); CPCOMMIT();
    load_chunk(4); CPCOMMIT();

    for (int c = 0; c < 64; c++) {
        CPWAIT4();               // chunk c resident (<=4 groups pending)
        __syncthreads();         // all warps done with stage (c-1)%6 reuse target
        if (c + 5 < 64) load_chunk(c + 5);
        CPCOMMIT();
        compute_chunk(c);
    }

    // ---- epilogue ----
    const int g = lane >> 2, cp2 = (lane & 3) * 2;
    const size_t cbase = (size_t)bp * PLANE + (size_t)rt * 131072 + (size_t)bct * CCB;
#pragma unroll
    for (int mt = 0; mt < 4; mt++) {
#pragma unroll
        for (int nt = 0; nt < 4; nt++) {
            int r0 = wm * 64 + mt * 16 + g;
            int col = wn * 32 + nt * 8 + cp2;
            float v0 = acc[mt][nt][0], v1 = acc[mt][nt][1];
            float v2 = acc[mt][nt][2], v3 = acc[mt][nt][3];
            size_t o0 = cbase + (size_t)r0 * CRI + col;
            size_t o1 = cbase + (size_t)(r0 + 8) * CRI + col;
            if (Cf) {
                float b0 = bias[bct * 128 + col], b1 = bias[bct * 128 + col + 1];
                *(float2*)(Cf + o0) = make_float2(v0 + b0, v1 + b1);
                *(float2*)(Cf + o1) = make_float2(v2 + b0, v3 + b1);
            } else {
                uint32_t hh, ll;
                packsplit2(v0, v1, hh, ll);
                *(uint32_t*)(Ch + o0) = hh; *(uint32_t*)(Cl + o0) = ll;
                packsplit2(v2, v3, hh, ll);
                *(uint32_t*)(Ch + o1) = hh; *(uint32_t*)(Cl + o1) = ll;
            }
        }
    }
}

// ======================= mma attention (bf16-split, register-resident P) =====
// One CTA per (b,h). Warp w owns rows w*16..w*16+15 (full 128 cols).
// Output: single fp16 plane (feeds final fp16 GEMM).
// smem: Q stages@0 (4 x 12288: h@0 l@6144), K/V stages@49152 (4 x 8704).
#define ATT_SMEM 83968
#define ATT_KST  49152u

__global__ __launch_bounds__(256, 1) void attn_mma(
    const bf16* __restrict__ ohb, const bf16* __restrict__ olb,
    __half* __restrict__ atth)
{
    extern __shared__ __align__(1024) char smem[];
    const uint32_t sb = s2u(smem);
    const int tid = threadIdx.x;
    const int lane = tid & 31, w = tid >> 5;
    const size_t bhoff = (size_t)blockIdx.x * 16384;

    // plane order in ohb: 0 qw, 1 kw, 2 vw, 3 qp, 4 kp, 5 qc, 6 kc
    const int qpl[3] = { 0, 3, 5 }, kpl[3] = { 1, 4, 6 };

    const int s8 = lane >> 3, r8 = lane & 7;
    const uint32_t aLane = (uint32_t)(((s8 & 1) * 8 + r8) * 48 + (s8 >> 1) * 16);
    const uint32_t kr = (uint32_t)(lane & 15);
    const uint32_t nf = (uint32_t)((lane >> 4) * 8);
    const uint32_t wrow48 = (uint32_t)(w * 16 * 48);

    const int qrow = tid >> 1, qhalf = tid & 1;
    const uint32_t qdst = (uint32_t)(qrow * 48 + qhalf * 16);
    const int krow = tid >> 4, kseg = tid & 15;
    const uint32_t kdst = (uint32_t)(krow * 272 + kseg * 16);

    auto loadQK = [&](int it) {
        int s = it >> 3, c = it & 7;
        uint32_t qs = sb + (uint32_t)((it & 3) * 12288) + qdst;
        size_t qsrc = (size_t)qpl[s] * PLANE + bhoff + (size_t)qrow * 128 + c * 16 + qhalf * 8;
        CP16(qs,        ohb + qsrc);
        CP16(qs + 6144, olb + qsrc);
        uint32_t ks = sb + ATT_KST + (uint32_t)((it & 3) * 8704) + kdst;
        size_t ksrc = (size_t)kpl[s] * PLANE + bhoff + (size_t)(c * 16 + krow) * 128 + kseg * 8;
        CP16(ks,        ohb + ksrc);
        CP16(ks + 4352, olb + ksrc);
    };
    auto loadV = [&](int v) {
        uint32_t ks = sb + ATT_KST + (uint32_t)((v & 3) * 8704) + kdst;
        size_t ksrc = 2ull * PLANE + bhoff + (size_t)(v * 16 + krow) * 128 + kseg * 8;
        CP16(ks,        ohb + ksrc);
        CP16(ks + 4352, olb + ksrc);
    };

    float acc[16][4];
#pragma unroll
    for (int i = 0; i < 16; i++)
#pragma unroll
        for (int j = 0; j < 4; j++) acc[i][j] = 0.f;

    loadQK(0); CPCOMMIT();
    loadQK(1); CPCOMMIT();
    loadQK(2); CPCOMMIT();

    // ---- Phase 1: sim (24 iters = 3 streams x 8 k-chunks) ----
    for (int it = 0; it < 24; it++) {
        CPWAIT2();
        __syncthreads();
        if (it + 3 < 24) loadQK(it + 3);
        CPCOMMIT();

        const uint32_t qs = sb + (uint32_t)((it & 3) * 12288);
        const uint32_t ks = sb + ATT_KST + (uint32_t)((it & 3) * 8704);
        uint32_t ah[4], al[4];
        ldsm4(ah, qs + wrow48 + aLane);
        ldsm4(al, qs + 6144 + wrow48 + aLane);
#pragma unroll
        for (int gp = 0; gp < 4; gp++) {
            uint32_t b0h[4], b0l[4], b1h[4], b1l[4];
            uint32_t a0 = ks + kr * 272 + ((2 * gp) * 16 + nf) * 2;
            uint32_t a1 = ks + kr * 272 + ((2 * gp + 1) * 16 + nf) * 2;
            ldsm4t(b0h, a0); ldsm4t(b0l, a0 + 4352);
            ldsm4t(b1h, a1); ldsm4t(b1l, a1 + 4352);
            float* c0 = acc[4 * gp],     *c1 = acc[4 * gp + 1];
            float* c2 = acc[4 * gp + 2], *c3 = acc[4 * gp + 3];
            mma_bf16(c0, ah, b0h);     mma_bf16(c1, ah, b0h + 2);
            mma_bf16(c2, ah, b1h);     mma_bf16(c3, ah, b1h + 2);
            mma_bf16(c0, al, b0h);     mma_bf16(c1, al, b0h + 2);
            mma_bf16(c2, al, b1h);     mma_bf16(c3, al, b1h + 2);
            mma_bf16(c0, ah, b0l);     mma_bf16(c1, ah, b0l + 2);
            mma_bf16(c2, ah, b1l);     mma_bf16(c3, ah, b1l + 2);
        }
    }

    // drain QK traffic, then prefetch V into stages 0..2 (overlaps softmax)
    CPWAIT0();
    __syncthreads();
    loadV(0); CPCOMMIT();
    loadV(1); CPCOMMIT();
    loadV(2); CPCOMMIT();

    // ---- Phase 2: softmax (warp-local; lane rows g and g+8) ----
    const float SC = 0.08838834764831845f;   // 128^-0.5
    float m0 = -1e30f, m1 = -1e30f;
#pragma unroll
    for (int nt = 0; nt < 16; nt++) {
#pragma unroll
        for (int j = 0; j < 4; j++) acc[nt][j] *= SC;
        m0 = fmaxf(m0, fmaxf(acc[nt][0], acc[nt][1]));
        m1 = fmaxf(m1, fmaxf(acc[nt][2], acc[nt][3]));
    }
    m0 = fmaxf(m0, __shfl_xor_sync(0xffffffffu, m0, 1));
    m0 = fmaxf(m0, __shfl_xor_sync(0xffffffffu, m0, 2));
    m1 = fmaxf(m1, __shfl_xor_sync(0xffffffffu, m1, 1));
    m1 = fmaxf(m1, __shfl_xor_sync(0xffffffffu, m1, 2));
    float sum0 = 0.f, sum1 = 0.f;
#pragma unroll
    for (int nt = 0; nt < 16; nt++) {
        acc[nt][0] = __expf(acc[nt][0] - m0); sum0 += acc[nt][0];
        acc[nt][1] = __expf(acc[nt][1] - m0); sum0 += acc[nt][1];
        acc[nt][2] = __expf(acc[nt][2] - m1); sum1 += acc[nt][2];
        acc[nt][3] = __expf(acc[nt][3] - m1); sum1 += acc[nt][3];
    }
    sum0 += __shfl_xor_sync(0xffffffffu, sum0, 1);
    sum0 += __shfl_xor_sync(0xffffffffu, sum0, 2);
    sum1 += __shfl_xor_sync(0xffffffffu, sum1, 1);
    sum1 += __shfl_xor_sync(0xffffffffu, sum1, 2);
    const float inv0 = 1.f / sum0, inv1 = 1.f / sum1;

    // ---- repack P into A-fragments (C-frag layout == A-frag layout) ----
    uint32_t ph[8][4], pl[8][4];
#pragma unroll
    for (int c = 0; c < 8; c++) {
        packsplit2(acc[2*c][0]   * inv0, acc[2*c][1]   * inv0, ph[c][0], pl[c][0]);
        packsplit2(acc[2*c][2]   * inv1, acc[2*c][3]   * inv1, ph[c][1], pl[c][1]);
        packsplit2(acc[2*c+1][0] * inv0, acc[2*c+1][1] * inv0, ph[c][2], pl[c][2]);
        packsplit2(acc[2*c+1][2] * inv1, acc[2*c+1][3] * inv1, ph[c][3], pl[c][3]);
    }
#pragma unroll
    for (int i = 0; i < 16; i++)
#pragma unroll
        for (int j = 0; j < 4; j++) acc[i][j] = 0.f;

    // ---- Phase 3: out = P * V (8 k-chunks) ----
    for (int v = 0; v < 8; v++) {
        CPWAIT2();
        __syncthreads();
        if (v + 3 < 8) loadV(v + 3);
        CPCOMMIT();

        const uint32_t ks = sb + ATT_KST + (uint32_t)((v & 3) * 8704);
#pragma unroll
        for (int gp = 0; gp < 4; gp++) {
            uint32_t b0h[4], b0l[4], b1h[4], b1l[4];
            uint32_t a0 = ks + kr * 272 + ((2 * gp) * 16 + nf) * 2;
            uint32_t a1 = ks + kr * 272 + ((2 * gp + 1) * 16 + nf) * 2;
            ldsm4t(b0h, a0); ldsm4t(b0l, a0 + 4352);
            ldsm4t(b1h, a1); ldsm4t(b1l, a1 + 4352);
            float* c0 = acc[4 * gp],     *c1 = acc[4 * gp + 1];
            float* c2 = acc[4 * gp + 2], *c3 = acc[4 * gp + 3];
            mma_bf16(c0, ph[v], b0h);  mma_bf16(c1, ph[v], b0h + 2);
            mma_bf16(c2, ph[v], b1h);  mma_bf16(c3, ph[v], b1h + 2);
            mma_bf16(c0, pl[v], b0h);  mma_bf16(c1, pl[v], b0h + 2);
            mma_bf16(c2, pl[v], b1h);  mma_bf16(c3, pl[v], b1h + 2);
            mma_bf16(c0, ph[v], b0l);  mma_bf16(c1, ph[v], b0l + 2);
            mma_bf16(c2, ph[v], b1l);  mma_bf16(c3, ph[v], b1l + 2);
        }
    }

    // ---- write att as fp16 plane ----
    {
        const int g = lane >> 2, c2 = (lane & 3) * 2;
        const size_t r0 = bhoff + (size_t)(w * 16 + g) * 128;
#pragma unroll
        for (int nt = 0; nt < 16; nt++) {
            int col = nt * 8 + c2;
            *(uint32_t*)(atth + r0 + col) = packh2(acc[nt][0], acc[nt][1]);
            *(uint32_t*)(atth + r0 + 8 * 128 + col) = packh2(acc[nt][2], acc[nt][3]);
        }
    }
}

// ======================= launch ==============================================
extern "C" void kernel_launch(void* const* d_in, const int* in_sizes, int n_in,
                              void* d_out, int out_size)
{
    (void)in_sizes; (void)n_in; (void)out_size;
    const float* inp[3] = { (const float*)d_in[0], (const float*)d_in[1],
                            (const float*)d_in[2] };
    const float* W[8] = { (const float*)d_in[3], (const float*)d_in[4],
                          (const float*)d_in[5], (const float*)d_in[6],
                          (const float*)d_in[7], (const float*)d_in[8],
                          (const float*)d_in[9], (const float*)d_in[10] };
    const float* bo = (const float*)d_in[11];
    float* out = (float*)d_out;

    void* symp = nullptr;
    cudaGetSymbolAddress(&symp, g_bf);
    bf16* P = (bf16*)symp;
    __half* infp = (__half*)P;                   // 3 fp16 input planes [0,3)
    bf16*   ohb  = P + 3ull * PLANE;             // 7 bf16 hi planes   [3,10)
    bf16*   olb  = P + 10ull * PLANE;            // 7 bf16 lo planes   [10,17)
    __half* atth = (__half*)(P + 17ull * PLANE); // 1 fp16 att plane   [17,18)
    __half* wfp  = (__half*)(P + 18ull * PLANE); // 8 fp16 weight planes

    cudaFuncSetAttribute(gemm_fp, cudaFuncAttributeMaxDynamicSharedMemorySize, GEMM_SMEM);
    cudaFuncSetAttribute(attn_mma, cudaFuncAttributeMaxDynamicSharedMemorySize, ATT_SMEM);

    // 0) convert inputs to fp16 planes
    split_all<<<dim3(16384, 3), 256>>>(inp[0], inp[1], inp[2], infp);

    // 1-2) transpose weights -> fp16 planes [N][K]
    dim3 tgrid(32, 32, 4), tblk(32, 8);
    transpose4<<<tgrid, tblk>>>(W[0], W[1], W[2], W[3], wfp);
    transpose4<<<tgrid, tblk>>>(W[4], W[5], W[6], W[7], wfp + 4ull * WPLANE);

    // 3) ALL projections in one launch (fp16 single pass) -> bf16 hi/lo planes
    gemm_fp<<<dim3(56, 128), 256, GEMM_SMEM>>>(
        infp, wfp, nullptr, ohb, olb, nullptr, 128, 1024, 16384, 128, 1);

    // 4) attention (bf16-split) -> fp16 att plane
    attn_mma<<<1024, 256, ATT_SMEM>>>(ohb, olb, atth);

    // 5) final GEMM: att * Wo^T + bias -> f32 out (row-major)
    gemm_fp<<<dim3(8, 128), 256, GEMM_SMEM>>>(
        atth, wfp + 7ull * WPLANE,
        out, nullptr, nullptr, bo, 16384, 128, 128, 1024, 0);
}